// round 3
// baseline (speedup 1.0000x reference)
#include <cuda_runtime.h>
#include <math.h>

#define HID 256
#define MAXN 100000

// ---------------- scratch (static device globals: no allocation allowed) ----
static __device__ float g_bufH[(size_t)MAXN * HID];   // ping
static __device__ float g_bufA[(size_t)MAXN * HID];   // pong
static __device__ int   g_deg[MAXN];
static __device__ float g_dinv[MAXN];
static __device__ float g_sum[HID];
static __device__ float g_sumsq[HID];
static __device__ float g_scale[HID];
static __device__ float g_shift[HID];

// ---------------- degree ----------------------------------------------------
__global__ void k_deg_init(int N) {
    int i = blockIdx.x * blockDim.x + threadIdx.x;
    if (i < N) g_deg[i] = 1;                 // self-loop
}

__global__ void k_deg_count(const int* __restrict__ dst, int E) {
    int e = blockIdx.x * blockDim.x + threadIdx.x;
    if (e < E) atomicAdd(&g_deg[dst[e]], 1);
}

__global__ void k_dinv(int N) {
    int i = blockIdx.x * blockDim.x + threadIdx.x;
    if (i < N) g_dinv[i] = rsqrtf((float)g_deg[i]);
}

// ---------------- SGEMM: C[M,Nc] = A[M,K] @ B[K,Nc] -------------------------
// 128x128 block tile, BK=8, 256 threads, 8x8 per-thread micro-tile.
__global__ __launch_bounds__(256, 2)
void k_gemm(const float* __restrict__ A, const float* __restrict__ B,
            float* __restrict__ C, int M, int K, int Nc) {
    __shared__ float As[8][128];
    __shared__ float Bs[8][128];

    const int tid = threadIdx.x;
    const int tx = tid & 15;         // 0..15 -> cols
    const int ty = tid >> 4;         // 0..15 -> rows
    const int m0 = blockIdx.x * 128;
    const int n0 = blockIdx.y * 128;

    // load mapping
    const int arow = tid >> 1;            // 0..127
    const int acol = (tid & 1) * 4;       // 0 or 4
    const int brow = tid >> 5;            // 0..7
    const int bcol = (tid & 31) * 4;      // 0..124

    float acc[8][8];
#pragma unroll
    for (int i = 0; i < 8; i++)
#pragma unroll
        for (int j = 0; j < 8; j++) acc[i][j] = 0.0f;

    for (int k0 = 0; k0 < K; k0 += 8) {
        // A tile (transposed into smem)
        float4 av = make_float4(0.f, 0.f, 0.f, 0.f);
        int gm = m0 + arow;
        if (gm < M)
            av = *(const float4*)&A[(size_t)gm * K + k0 + acol];
        As[acol + 0][arow] = av.x;
        As[acol + 1][arow] = av.y;
        As[acol + 2][arow] = av.z;
        As[acol + 3][arow] = av.w;
        // B tile
        float4 bv = *(const float4*)&B[(size_t)(k0 + brow) * Nc + n0 + bcol];
        *(float4*)&Bs[brow][bcol] = bv;
        __syncthreads();

#pragma unroll
        for (int k = 0; k < 8; k++) {
            float4 a0 = *(float4*)&As[k][ty * 8];
            float4 a1 = *(float4*)&As[k][ty * 8 + 4];
            float4 b0 = *(float4*)&Bs[k][tx * 8];
            float4 b1 = *(float4*)&Bs[k][tx * 8 + 4];
            float am[8] = {a0.x, a0.y, a0.z, a0.w, a1.x, a1.y, a1.z, a1.w};
            float bn[8] = {b0.x, b0.y, b0.z, b0.w, b1.x, b1.y, b1.z, b1.w};
#pragma unroll
            for (int i = 0; i < 8; i++)
#pragma unroll
                for (int j = 0; j < 8; j++) acc[i][j] = fmaf(am[i], bn[j], acc[i][j]);
        }
        __syncthreads();
    }

#pragma unroll
    for (int i = 0; i < 8; i++) {
        int gm = m0 + ty * 8 + i;
        if (gm < M) {
            float4 c0 = make_float4(acc[i][0], acc[i][1], acc[i][2], acc[i][3]);
            float4 c1 = make_float4(acc[i][4], acc[i][5], acc[i][6], acc[i][7]);
            *(float4*)&C[(size_t)gm * Nc + n0 + tx * 8]     = c0;
            *(float4*)&C[(size_t)gm * Nc + n0 + tx * 8 + 4] = c1;
        }
    }
}

// ---------------- aggregation ----------------------------------------------
// agg = bias + h * dinv^2 (self-loop term), elementwise float4
__global__ void k_agg_init(const float* __restrict__ h, const float* __restrict__ bias,
                           float* __restrict__ agg, long total4) {
    long i4 = (long)blockIdx.x * blockDim.x + threadIdx.x;
    if (i4 >= total4) return;
    int row  = (int)(i4 >> 6);            // HID/4 = 64 float4 per row
    int col4 = ((int)i4 & 63) * 4;
    float d = g_dinv[row];
    float s = d * d;
    float4 hv = *(const float4*)&h[i4 * 4];
    float4 bv = *(const float4*)&bias[col4];
    float4 o;
    o.x = fmaf(hv.x, s, bv.x);
    o.y = fmaf(hv.y, s, bv.y);
    o.z = fmaf(hv.z, s, bv.z);
    o.w = fmaf(hv.w, s, bv.w);
    *(float4*)&agg[i4 * 4] = o;
}

// one edge per 64 threads; each thread does one float4 red to L2
__global__ void k_scatter(const float* __restrict__ h, float* __restrict__ agg,
                          const int* __restrict__ src, const int* __restrict__ dst,
                          int E) {
    long t = (long)blockIdx.x * blockDim.x + threadIdx.x;
    int e = (int)(t >> 6);
    if (e >= E) return;
    int j = ((int)t & 63) * 4;
    int s = src[e];
    int d = dst[e];
    float coef = g_dinv[s] * g_dinv[d];
    float4 hv = *(const float4*)&h[(size_t)s * HID + j];
    float vx = hv.x * coef, vy = hv.y * coef, vz = hv.z * coef, vw = hv.w * coef;
    float* p = &agg[(size_t)d * HID + j];
    asm volatile("red.global.add.v4.f32 [%0], {%1, %2, %3, %4};"
                 :: "l"(p), "f"(vx), "f"(vy), "f"(vz), "f"(vw) : "memory");
}

// ---------------- batchnorm -------------------------------------------------
__global__ void k_bn_zero() {
    int c = threadIdx.x;
    g_sum[c] = 0.0f;
    g_sumsq[c] = 0.0f;
}

__global__ void k_bn_stats(const float* __restrict__ h, int N) {
    int col = threadIdx.x;                  // 256 threads = 256 columns
    float s = 0.0f, ss = 0.0f;
    for (int r = blockIdx.x; r < N; r += gridDim.x) {
        float v = h[(size_t)r * HID + col];
        s += v;
        ss += v * v;
    }
    atomicAdd(&g_sum[col], s);
    atomicAdd(&g_sumsq[col], ss);
}

__global__ void k_bn_finalize(const float* __restrict__ gamma,
                              const float* __restrict__ beta, float Nf) {
    int c = threadIdx.x;
    float mu = g_sum[c] / Nf;
    float var = g_sumsq[c] / Nf - mu * mu;
    var = fmaxf(var, 0.0f);
    float a = gamma[c] * rsqrtf(var + 1e-5f);
    g_scale[c] = a;
    g_shift[c] = beta[c] - a * mu;
}

__global__ void k_bn_apply_relu(const float* __restrict__ in, float* __restrict__ out,
                                long total4) {
    long i4 = (long)blockIdx.x * blockDim.x + threadIdx.x;
    if (i4 >= total4) return;
    int col4 = ((int)i4 & 63) * 4;
    float4 v = *(const float4*)&in[i4 * 4];
    float4 a = *(const float4*)&g_scale[col4];
    float4 c = *(const float4*)&g_shift[col4];
    float4 o;
    o.x = fmaxf(fmaf(v.x, a.x, c.x), 0.0f);
    o.y = fmaxf(fmaf(v.y, a.y, c.y), 0.0f);
    o.z = fmaxf(fmaf(v.z, a.z, c.z), 0.0f);
    o.w = fmaxf(fmaf(v.w, a.w, c.w), 0.0f);
    *(float4*)&out[i4 * 4] = o;
}

// ---------------- launch ----------------------------------------------------
extern "C" void kernel_launch(void* const* d_in, const int* in_sizes, int n_in,
                              void* d_out, int out_size) {
    const float* x   = (const float*)d_in[0];
    const int*   ei  = (const int*)  d_in[1];
    const float* W1  = (const float*)d_in[2];
    const float* b1  = (const float*)d_in[3];
    const float* gm1 = (const float*)d_in[4];
    const float* be1 = (const float*)d_in[5];
    const float* W2  = (const float*)d_in[6];
    const float* b2  = (const float*)d_in[7];
    const float* gm2 = (const float*)d_in[8];
    const float* be2 = (const float*)d_in[9];

    const int H  = in_sizes[3];            // 256
    const int K1 = in_sizes[2] / H;        // 384
    const int N  = in_sizes[0] / K1;       // 100000
    const int E  = in_sizes[1] / 2;        // 800000
    const int* src = ei;
    const int* dst = ei + E;

    float* bufH;
    float* bufA;
    cudaGetSymbolAddress((void**)&bufH, g_bufH);
    cudaGetSymbolAddress((void**)&bufA, g_bufA);
    float* out = (float*)d_out;

    const long total4 = (long)N * H / 4;
    const int  ew     = (int)((total4 + 255) / 256);
    const int  scat_b = (int)(((long)E * 64 + 255) / 256);
    dim3 gg((N + 127) / 128, H / 128);

    // degrees + normalization coefs
    k_deg_init<<<(N + 255) / 256, 256>>>(N);
    k_deg_count<<<(E + 255) / 256, 256>>>(dst, E);
    k_dinv<<<(N + 255) / 256, 256>>>(N);

    // ---- layer 1 ----
    k_gemm<<<gg, 256>>>(x, W1, bufH, N, K1, H);
    k_agg_init<<<ew, 256>>>(bufH, b1, bufA, total4);
    k_scatter<<<scat_b, 256>>>(bufH, bufA, src, dst, E);
    k_bn_zero<<<1, 256>>>();
    k_bn_stats<<<512, 256>>>(bufA, N);
    k_bn_finalize<<<1, 256>>>(gm1, be1, (float)N);
    k_bn_apply_relu<<<ew, 256>>>(bufA, bufH, total4);

    // ---- layer 2 ----
    k_gemm<<<gg, 256>>>(bufH, W2, bufA, N, H, H);
    k_agg_init<<<ew, 256>>>(bufA, b2, out, total4);
    k_scatter<<<scat_b, 256>>>(bufA, out, src, dst, E);
    k_bn_zero<<<1, 256>>>();
    k_bn_stats<<<512, 256>>>(out, N);
    k_bn_finalize<<<1, 256>>>(gm2, be2, (float)N);
    k_bn_apply_relu<<<ew, 256>>>(out, out, total4);
}

// round 9
// speedup vs baseline: 1.3491x; 1.3491x over previous
#include <cuda_runtime.h>
#include <cuda_bf16.h>
#include <math.h>
#include <stdint.h>

#define HID 256
#define MAXN 100000
#define MAXK 384

// ---------------- scratch (static device globals: no allocation allowed) ----
static __device__ float g_bufH[(size_t)MAXN * HID];   // ping
static __device__ float g_bufA[(size_t)MAXN * HID];   // pong
static __device__ int   g_deg[MAXN];
static __device__ float g_dinv[MAXN];
static __device__ float g_sum[HID];
static __device__ float g_sumsq[HID];
static __device__ float g_scale[HID];
static __device__ float g_shift[HID];
// split-bf16 transposed weights: [N=HID][K] row-major (= .col operand for mma)
static __device__ __nv_bfloat16 g_B1h[(size_t)HID * MAXK];
static __device__ __nv_bfloat16 g_B1l[(size_t)HID * MAXK];
static __device__ __nv_bfloat16 g_B2h[(size_t)HID * HID];
static __device__ __nv_bfloat16 g_B2l[(size_t)HID * HID];

// ---------------- helpers ----------------------------------------------------
__device__ __forceinline__ uint32_t smem_u32(const void* p) {
    uint32_t a;
    asm("{ .reg .u64 t; cvta.to.shared.u64 t, %1; cvt.u32.u64 %0, t; }"
        : "=r"(a) : "l"(p));
    return a;
}
__device__ __forceinline__ uint32_t pack2(float a, float b) {
    __nv_bfloat162 t = __floats2bfloat162_rn(a, b);
    return *reinterpret_cast<uint32_t*>(&t);
}
__device__ __forceinline__ void sts128(uint32_t a, uint32_t x, uint32_t y,
                                       uint32_t z, uint32_t w) {
    asm volatile("st.shared.v4.b32 [%0], {%1,%2,%3,%4};"
                 :: "r"(a), "r"(x), "r"(y), "r"(z), "r"(w) : "memory");
}

#define LDSM4(r, a) \
    asm volatile("ldmatrix.sync.aligned.m8n8.x4.shared.b16 {%0,%1,%2,%3}, [%4];" \
                 : "=r"((r)[0]), "=r"((r)[1]), "=r"((r)[2]), "=r"((r)[3]) : "r"(a))

#define MMA16816(c, a, b0, b1) \
    asm volatile("mma.sync.aligned.m16n8k16.row.col.f32.bf16.bf16.f32 " \
                 "{%0,%1,%2,%3},{%4,%5,%6,%7},{%8,%9},{%0,%1,%2,%3};" \
                 : "+f"((c)[0]), "+f"((c)[1]), "+f"((c)[2]), "+f"((c)[3]) \
                 : "r"((a)[0]), "r"((a)[1]), "r"((a)[2]), "r"((a)[3]), \
                   "r"(b0), "r"(b1))

// ---------------- degree ----------------------------------------------------
__global__ void k_deg_init(int N) {
    int i = blockIdx.x * blockDim.x + threadIdx.x;
    if (i < N) g_deg[i] = 1;                 // self-loop
}
__global__ void k_deg_count(const int* __restrict__ dst, int E) {
    int e = blockIdx.x * blockDim.x + threadIdx.x;
    if (e < E) atomicAdd(&g_deg[dst[e]], 1);
}
__global__ void k_dinv(int N) {
    int i = blockIdx.x * blockDim.x + threadIdx.x;
    if (i < N) g_dinv[i] = rsqrtf((float)g_deg[i]);
}

// ---------------- weight transpose + bf16 split -----------------------------
// B[k][n] (f32, K x HID) -> Bt_hi/Bt_lo[n][k] (bf16, HID x K)
__global__ void k_convB(const float* __restrict__ B, __nv_bfloat16* __restrict__ th,
                        __nv_bfloat16* __restrict__ tl, int K) {
    int i = blockIdx.x * blockDim.x + threadIdx.x;
    if (i >= K * HID) return;
    int k = i / HID, n = i % HID;
    float v = B[i];
    float h = __bfloat162float(__float2bfloat16_rn(v));
    th[(size_t)n * K + k] = __float2bfloat16_rn(h);
    tl[(size_t)n * K + k] = __float2bfloat16_rn(v - h);
}

// ---------------- warp-MMA GEMM: C[M,256] = A[M,K] @ B[K,256] ---------------
// CTA 128x128, 8 warps (warp tile 32x64), BK=32, double-buffered smem.
// Split-bf16 (3 mma products) for ~fp32 accuracy. Smem stride 40 bf16 (80B):
// conflict-free ldmatrix.
#define PAD 40
#define OAH 0
#define OAL 10240
#define OBH 20480
#define OBL 30720
#define STG_SZ 40960
#define SM_TOT (2 * STG_SZ)

__global__ __launch_bounds__(256, 1)
void k_gemm_mma(const float* __restrict__ A,
                const __nv_bfloat16* __restrict__ Bth,
                const __nv_bfloat16* __restrict__ Btl,
                float* __restrict__ C, int M, int K) {
    extern __shared__ char smem[];
    const uint32_t sb = smem_u32(smem);
    const int tid = threadIdx.x;
    const int lane = tid & 31;
    const int wid = tid >> 5;
    const int m0 = blockIdx.x * 128;
    const int n0 = blockIdx.y * 128;
    const int m0w = (wid & 3) * 32;
    const int n0w = (wid >> 2) * 64;

    // gmem load mapping: thread -> (row = tid/2, 16 consecutive cols)
    const int row = tid >> 1;
    const int cg  = (tid & 1) * 16;
    const bool avalid = (m0 + row) < M;
    const float*         ap  = A   + (size_t)(m0 + row) * K + cg;
    const __nv_bfloat16* bhp = Bth + (size_t)(n0 + row) * K + cg;
    const __nv_bfloat16* blp = Btl + (size_t)(n0 + row) * K + cg;
    const uint32_t stsOff = (uint32_t)(row * PAD + cg) * 2;

    // ldmatrix base addressing
    const int lrow = lane & 15;
    const int lcol = (lane >> 4) * 8;
    const uint32_t aB = sb + OAH + (uint32_t)((m0w + lrow) * PAD + lcol) * 2;
    const uint32_t bB = sb + OBH + (uint32_t)((n0w + lrow) * PAD + lcol) * 2;

    float acc[2][8][4];
#pragma unroll
    for (int i = 0; i < 2; i++)
#pragma unroll
        for (int j = 0; j < 8; j++)
#pragma unroll
            for (int q = 0; q < 4; q++) acc[i][j][q] = 0.0f;

    float4 pa[4];
    uint4  pbh[2], pbl[2];

    // prefetch tile 0
#pragma unroll
    for (int i = 0; i < 4; i++)
        pa[i] = avalid ? *(const float4*)(ap + i * 4)
                       : make_float4(0.f, 0.f, 0.f, 0.f);
    pbh[0] = *(const uint4*)(bhp);     pbh[1] = *(const uint4*)(bhp + 8);
    pbl[0] = *(const uint4*)(blp);     pbl[1] = *(const uint4*)(blp + 8);

    // store tile 0 into stage 0
    {
        uint32_t hr[8], lr[8];
#pragma unroll
        for (int i = 0; i < 4; i++) {
            float fx[4] = {pa[i].x, pa[i].y, pa[i].z, pa[i].w};
#pragma unroll
            for (int j = 0; j < 2; j++) {
                float v0 = fx[2 * j], v1 = fx[2 * j + 1];
                float h0 = __bfloat162float(__float2bfloat16_rn(v0));
                float h1 = __bfloat162float(__float2bfloat16_rn(v1));
                hr[i * 2 + j] = pack2(h0, h1);
                lr[i * 2 + j] = pack2(v0 - h0, v1 - h1);
            }
        }
        uint32_t s = sb + stsOff;
        sts128(s + OAH,      hr[0], hr[1], hr[2], hr[3]);
        sts128(s + OAH + 16, hr[4], hr[5], hr[6], hr[7]);
        sts128(s + OAL,      lr[0], lr[1], lr[2], lr[3]);
        sts128(s + OAL + 16, lr[4], lr[5], lr[6], lr[7]);
        sts128(s + OBH,      pbh[0].x, pbh[0].y, pbh[0].z, pbh[0].w);
        sts128(s + OBH + 16, pbh[1].x, pbh[1].y, pbh[1].z, pbh[1].w);
        sts128(s + OBL,      pbl[0].x, pbl[0].y, pbl[0].z, pbl[0].w);
        sts128(s + OBL + 16, pbl[1].x, pbl[1].y, pbl[1].z, pbl[1].w);
    }

    const int nch = K >> 5;
    for (int c = 0; c < nch; c++) {
        __syncthreads();
        const uint32_t stg = (uint32_t)(c & 1) * STG_SZ;

        // prefetch next tile (gmem -> regs), overlapped with compute below
        if (c + 1 < nch) {
            const int k0 = (c + 1) * 32;
#pragma unroll
            for (int i = 0; i < 4; i++)
                pa[i] = avalid ? *(const float4*)(ap + k0 + i * 4)
                               : make_float4(0.f, 0.f, 0.f, 0.f);
            pbh[0] = *(const uint4*)(bhp + k0);  pbh[1] = *(const uint4*)(bhp + k0 + 8);
            pbl[0] = *(const uint4*)(blp + k0);  pbl[1] = *(const uint4*)(blp + k0 + 8);
        }

        // compute on stage c&1
#pragma unroll
        for (int kk = 0; kk < 2; kk++) {
            const uint32_t ko = (uint32_t)(kk * 16 * 2);
            uint32_t ah[2][4], al[2][4];
            LDSM4(ah[0], aB + stg + ko);
            LDSM4(ah[1], aB + stg + ko + 16 * PAD * 2);
            LDSM4(al[0], aB + stg + ko + (OAL - OAH));
            LDSM4(al[1], aB + stg + ko + (OAL - OAH) + 16 * PAD * 2);
#pragma unroll
            for (int ni = 0; ni < 4; ni++) {
                uint32_t bh[4], bl[4];
                const uint32_t bo = bB + stg + ko + (uint32_t)(ni * 16 * PAD * 2);
                LDSM4(bh, bo);
                LDSM4(bl, bo + (OBL - OBH));
#pragma unroll
                for (int mi = 0; mi < 2; mi++) {
                    MMA16816(acc[mi][2 * ni],     ah[mi], bh[0], bh[2]);
                    MMA16816(acc[mi][2 * ni],     ah[mi], bl[0], bl[2]);
                    MMA16816(acc[mi][2 * ni],     al[mi], bh[0], bh[2]);
                    MMA16816(acc[mi][2 * ni + 1], ah[mi], bh[1], bh[3]);
                    MMA16816(acc[mi][2 * ni + 1], ah[mi], bl[1], bl[3]);
                    MMA16816(acc[mi][2 * ni + 1], al[mi], bh[1], bh[3]);
                }
            }
        }

        // store prefetched tile into the other stage
        if (c + 1 < nch) {
            uint32_t hr[8], lr[8];
#pragma unroll
            for (int i = 0; i < 4; i++) {
                float fx[4] = {pa[i].x, pa[i].y, pa[i].z, pa[i].w};
#pragma unroll
                for (int j = 0; j < 2; j++) {
                    float v0 = fx[2 * j], v1 = fx[2 * j + 1];
                    float h0 = __bfloat162float(__float2bfloat16_rn(v0));
                    float h1 = __bfloat162float(__float2bfloat16_rn(v1));
                    hr[i * 2 + j] = pack2(h0, h1);
                    lr[i * 2 + j] = pack2(v0 - h0, v1 - h1);
                }
            }
            uint32_t s = sb + (uint32_t)((c + 1) & 1) * STG_SZ + stsOff;
            sts128(s + OAH,      hr[0], hr[1], hr[2], hr[3]);
            sts128(s + OAH + 16, hr[4], hr[5], hr[6], hr[7]);
            sts128(s + OAL,      lr[0], lr[1], lr[2], lr[3]);
            sts128(s + OAL + 16, lr[4], lr[5], lr[6], lr[7]);
            sts128(s + OBH,      pbh[0].x, pbh[0].y, pbh[0].z, pbh[0].w);
            sts128(s + OBH + 16, pbh[1].x, pbh[1].y, pbh[1].z, pbh[1].w);
            sts128(s + OBL,      pbl[0].x, pbl[0].y, pbl[0].z, pbl[0].w);
            sts128(s + OBL + 16, pbl[1].x, pbl[1].y, pbl[1].z, pbl[1].w);
        }
    }

    // epilogue: each warp writes its 32x64 region
#pragma unroll
    for (int mi = 0; mi < 2; mi++) {
        const int r0 = m0 + m0w + mi * 16 + (lane >> 2);
#pragma unroll
        for (int half = 0; half < 2; half++) {
            const int r = r0 + half * 8;
            if (r < M) {
                float* crow = &C[(size_t)r * HID + n0 + n0w + (lane & 3) * 2];
#pragma unroll
                for (int nj = 0; nj < 8; nj++) {
                    float2 v = make_float2(acc[mi][nj][half * 2],
                                           acc[mi][nj][half * 2 + 1]);
                    *(float2*)(crow + nj * 8) = v;
                }
            }
        }
    }
}

// ---------------- aggregation ----------------------------------------------
__global__ void k_agg_init(const float* __restrict__ h, const float* __restrict__ bias,
                           float* __restrict__ agg, long total4) {
    long i4 = (long)blockIdx.x * blockDim.x + threadIdx.x;
    if (i4 >= total4) return;
    int row  = (int)(i4 >> 6);
    int col4 = ((int)i4 & 63) * 4;
    float d = g_dinv[row];
    float s = d * d;
    float4 hv = *(const float4*)&h[i4 * 4];
    float4 bv = *(const float4*)&bias[col4];
    float4 o;
    o.x = fmaf(hv.x, s, bv.x);
    o.y = fmaf(hv.y, s, bv.y);
    o.z = fmaf(hv.z, s, bv.z);
    o.w = fmaf(hv.w, s, bv.w);
    *(float4*)&agg[i4 * 4] = o;
}

__global__ void k_scatter(const float* __restrict__ h, float* __restrict__ agg,
                          const int* __restrict__ src, const int* __restrict__ dst,
                          int E) {
    long t = (long)blockIdx.x * blockDim.x + threadIdx.x;
    int e = (int)(t >> 6);
    if (e >= E) return;
    int j = ((int)t & 63) * 4;
    int s = src[e];
    int d = dst[e];
    float coef = g_dinv[s] * g_dinv[d];
    float4 hv = *(const float4*)&h[(size_t)s * HID + j];
    float vx = hv.x * coef, vy = hv.y * coef, vz = hv.z * coef, vw = hv.w * coef;
    float* p = &agg[(size_t)d * HID + j];
    asm volatile("red.global.add.v4.f32 [%0], {%1, %2, %3, %4};"
                 :: "l"(p), "f"(vx), "f"(vy), "f"(vz), "f"(vw) : "memory");
}

// ---------------- batchnorm -------------------------------------------------
__global__ void k_bn_zero() {
    int c = threadIdx.x;
    g_sum[c] = 0.0f;
    g_sumsq[c] = 0.0f;
}

__global__ void k_bn_stats(const float* __restrict__ h, int N) {
    int col = threadIdx.x;
    float s = 0.0f, ss = 0.0f;
    for (int r = blockIdx.x; r < N; r += gridDim.x) {
        float v = h[(size_t)r * HID + col];
        s += v;
        ss += v * v;
    }
    atomicAdd(&g_sum[col], s);
    atomicAdd(&g_sumsq[col], ss);
}

__global__ void k_bn_finalize(const float* __restrict__ gamma,
                              const float* __restrict__ beta, float Nf) {
    int c = threadIdx.x;
    float mu = g_sum[c] / Nf;
    float var = g_sumsq[c] / Nf - mu * mu;
    var = fmaxf(var, 0.0f);
    float a = gamma[c] * rsqrtf(var + 1e-5f);
    g_scale[c] = a;
    g_shift[c] = beta[c] - a * mu;
}

__global__ void k_bn_apply_relu(const float* __restrict__ in, float* __restrict__ out,
                                long total4) {
    long i4 = (long)blockIdx.x * blockDim.x + threadIdx.x;
    if (i4 >= total4) return;
    int col4 = ((int)i4 & 63) * 4;
    float4 v = *(const float4*)&in[i4 * 4];
    float4 a = *(const float4*)&g_scale[col4];
    float4 c = *(const float4*)&g_shift[col4];
    float4 o;
    o.x = fmaxf(fmaf(v.x, a.x, c.x), 0.0f);
    o.y = fmaxf(fmaf(v.y, a.y, c.y), 0.0f);
    o.z = fmaxf(fmaf(v.z, a.z, c.z), 0.0f);
    o.w = fmaxf(fmaf(v.w, a.w, c.w), 0.0f);
    *(float4*)&out[i4 * 4] = o;
}

// ---------------- launch ----------------------------------------------------
extern "C" void kernel_launch(void* const* d_in, const int* in_sizes, int n_in,
                              void* d_out, int out_size) {
    const float* x   = (const float*)d_in[0];
    const int*   ei  = (const int*)  d_in[1];
    const float* W1  = (const float*)d_in[2];
    const float* b1  = (const float*)d_in[3];
    const float* gm1 = (const float*)d_in[4];
    const float* be1 = (const float*)d_in[5];
    const float* W2  = (const float*)d_in[6];
    const float* b2  = (const float*)d_in[7];
    const float* gm2 = (const float*)d_in[8];
    const float* be2 = (const float*)d_in[9];

    const int H  = in_sizes[3];            // 256
    const int K1 = in_sizes[2] / H;        // 384
    const int N  = in_sizes[0] / K1;       // 100000
    const int E  = in_sizes[1] / 2;        // 800000
    const int* src = ei;
    const int* dst = ei + E;

    float* bufH;  float* bufA;
    __nv_bfloat16 *b1h, *b1l, *b2h, *b2l;
    cudaGetSymbolAddress((void**)&bufH, g_bufH);
    cudaGetSymbolAddress((void**)&bufA, g_bufA);
    cudaGetSymbolAddress((void**)&b1h, g_B1h);
    cudaGetSymbolAddress((void**)&b1l, g_B1l);
    cudaGetSymbolAddress((void**)&b2h, g_B2h);
    cudaGetSymbolAddress((void**)&b2l, g_B2l);
    float* out = (float*)d_out;

    cudaFuncSetAttribute(k_gemm_mma, cudaFuncAttributeMaxDynamicSharedMemorySize, SM_TOT);

    const long total4 = (long)N * H / 4;
    const int  ew     = (int)((total4 + 255) / 256);
    const int  scat_b = (int)(((long)E * 64 + 255) / 256);
    dim3 gg((N + 127) / 128, H / 128);

    // degrees + normalization coefs + weight conversion
    k_deg_init<<<(N + 255) / 256, 256>>>(N);
    k_deg_count<<<(E + 255) / 256, 256>>>(dst, E);
    k_dinv<<<(N + 255) / 256, 256>>>(N);
    k_convB<<<(K1 * H + 255) / 256, 256>>>(W1, b1h, b1l, K1);
    k_convB<<<(H * H + 255) / 256, 256>>>(W2, b2h, b2l, H);

    // ---- layer 1 ----
    k_gemm_mma<<<gg, 256, SM_TOT>>>(x, b1h, b1l, bufH, N, K1);
    k_agg_init<<<ew, 256>>>(bufH, b1, bufA, total4);
    k_scatter<<<scat_b, 256>>>(bufH, bufA, src, dst, E);
    k_bn_zero<<<1, 256>>>();
    k_bn_stats<<<512, 256>>>(bufA, N);
    k_bn_finalize<<<1, 256>>>(gm1, be1, (float)N);
    k_bn_apply_relu<<<ew, 256>>>(bufA, bufH, total4);

    // ---- layer 2 ----
    k_gemm_mma<<<gg, 256, SM_TOT>>>(bufH, b2h, b2l, bufA, N, H);
    k_agg_init<<<ew, 256>>>(bufA, b2, out, total4);
    k_scatter<<<scat_b, 256>>>(bufA, out, src, dst, E);
    k_bn_zero<<<1, 256>>>();
    k_bn_stats<<<512, 256>>>(out, N);
    k_bn_finalize<<<1, 256>>>(gm2, be2, (float)N);
    k_bn_apply_relu<<<ew, 256>>>(out, out, total4);
}